// round 8
// baseline (speedup 1.0000x reference)
#include <cuda_runtime.h>
#include <cstddef>

#define IMG_H 512
#define IMG_W 512
#define IMGF  (IMG_H * IMG_W * 3)   // floats per batch image
#define TILE_W 64
#define TILE_H 16

__constant__ float c_w[81];   // [ky][kx][ci][co] HWIO
__constant__ float c_b[3];

__device__ __forceinline__ void load_row_g(const float* __restrict__ Xb,
                                           int row_off, bool rvalid,
                                           bool zl, bool zr, float f[20])
{
#pragma unroll
    for (int j = 0; j < 5; j++) {
        float4 v = make_float4(0.f, 0.f, 0.f, 0.f);
        const int g = row_off + 4 * j;
        if (rvalid && g >= 0 && g + 3 < IMGF)
            v = *(const float4*)(Xb + g);
        f[4*j+0] = v.x; f[4*j+1] = v.y; f[4*j+2] = v.z; f[4*j+3] = v.w;
    }
    if (zl) { f[1]  = 0.f; f[2]  = 0.f; f[3]  = 0.f; }
    if (zr) { f[16] = 0.f; f[17] = 0.f; f[18] = 0.f; }
}

__device__ __forceinline__ void apply_row(const float f[20], float acc[12], const int wrow)
{
#pragma unroll
    for (int x = 0; x < 4; x++) {
#pragma unroll
        for (int dx = 0; dx < 3; dx++) {
#pragma unroll
            for (int ci = 0; ci < 3; ci++) {
                const float v = f[3*(x + dx) + ci + 1];
                const int wb = ((wrow*3 + dx)*3 + ci)*3;
                acc[x*3 + 0] += v * c_w[wb + 0];
                acc[x*3 + 1] += v * c_w[wb + 1];
                acc[x*3 + 2] += v * c_w[wb + 2];
            }
        }
    }
}

__global__ __launch_bounds__(128, 8)
void patchenc_v4_kernel(const float* __restrict__ X,
                        const float* __restrict__ pos_emb,
                        float* __restrict__ out)
{
    // PE slice: 64 local nf (4 rows x 16 cols), 12 float4 each, padded to 13.
    __shared__ float4 spe4[64 * 13];      // 13312 B
    __shared__ float4 sout4[768];         // 12288 B, output-ordered

    const int b  = blockIdx.z;
    const int h0 = blockIdx.y * TILE_H;
    const int w0 = blockIdx.x * TILE_W;
    const float* __restrict__ Xb = X + (size_t)b * IMGF;

    // ---- phase 0: coalesced PE-slice fill ----
    {
        const float4* pe4 = (const float4*)pos_emb;
        const int fr0 = h0 >> 2;          // fine-patch row base
        const int fc0 = w0 >> 2;          // fine-patch col base
#pragma unroll
        for (int k = 0; k < 6; k++) {
            const int p   = threadIdx.x + k * 128;   // 0..767
            const int lnf = p / 12;
            const int j   = p - lnf * 12;
            const int lr  = lnf >> 4;
            const int lc  = lnf & 15;
            spe4[lnf * 13 + j] = pe4[(size_t)(fr0 + lr) * 1536 + (fc0 + lc) * 12 + j];
        }
    }

    // ---- phase 1: conv (register-streamed, no smem, no barrier yet) ----
    const int txq = threadIdx.x & 15;     // x quad: gw0 = w0 + 4*txq
    const int tyq = threadIdx.x >> 4;     // 0..7:   gh0 = h0 + 2*tyq
    const int gh0 = h0 + 2 * tyq;

    const bool zl = (w0 == 0) && (txq == 0);
    const bool zr = (w0 == IMG_W - TILE_W) && (txq == 15);

    const int base_off = 3 * w0 + 12 * txq - 4;
    const int ROWF = 3 * IMG_W;

    float acc0[12], acc1[12];
#pragma unroll
    for (int x = 0; x < 4; x++)
#pragma unroll
        for (int c = 0; c < 3; c++) { acc0[x*3+c] = c_b[c]; acc1[x*3+c] = c_b[c]; }

    float f[20];
    {
        const int r = gh0 - 1;
        load_row_g(Xb, base_off + r * ROWF, r >= 0, zl, zr, f);
        apply_row(f, acc0, 0);
    }
    {
        load_row_g(Xb, base_off + gh0 * ROWF, true, zl, zr, f);
        apply_row(f, acc0, 1);
        apply_row(f, acc1, 0);
    }
    {
        load_row_g(Xb, base_off + (gh0 + 1) * ROWF, true, zl, zr, f);
        apply_row(f, acc0, 2);
        apply_row(f, acc1, 1);
    }
    {
        const int r = gh0 + 2;
        load_row_g(Xb, base_off + r * ROWF, r < IMG_H, zl, zr, f);
        apply_row(f, acc1, 2);
    }

    __syncthreads();   // PE fill complete (long conv phase hid its latency)

    // ---- phase 2: PE add (smem) + store into output-ordered smem ----
#pragma unroll
    for (int k = 0; k < 2; k++) {
        const float* acc = (k == 0) ? acc0 : acc1;
        const int gh = gh0 + k;
        const int lr = (gh - h0) >> 2;                       // 0..3
        const float4* pb = &spe4[(lr * 16 + txq) * 13 + (gh & 3) * 3];
        const float4 p0 = pb[0], p1 = pb[1], p2 = pb[2];

        const int pch  = txq >> 2;                           // patch col 0..3
        float4* so = &sout4[pch * 192 + (gh & 15) * 12 + (txq & 3) * 3];
        so[0] = make_float4(acc[0] + p0.x, acc[1]  + p0.y, acc[2]  + p0.z, acc[3]  + p0.w);
        so[1] = make_float4(acc[4] + p1.x, acc[5]  + p1.y, acc[6]  + p1.z, acc[7]  + p1.w);
        so[2] = make_float4(acc[8] + p2.x, acc[9]  + p2.y, acc[10] + p2.z, acc[11] + p2.w);
    }

    __syncthreads();

    // ---- phase 3: perfectly linear 12KB copy to global ----
    {
        const int np0 = (h0 >> 4) * 32 + (w0 >> 4);          // 4 consecutive patches
        float4* dst = (float4*)out + (size_t)b * 196608 + (size_t)np0 * 192;
#pragma unroll
        for (int k = 0; k < 6; k++) {
            const int v = threadIdx.x + k * 128;             // 0..767
            dst[v] = sout4[v];
        }
    }
}

extern "C" void kernel_launch(void* const* d_in, const int* in_sizes, int n_in,
                              void* d_out, int out_size)
{
    const float* X  = (const float*)d_in[0];
    const float* Kw = (const float*)d_in[1];
    const float* Bb = (const float*)d_in[2];
    const float* PE = (const float*)d_in[3];

    cudaMemcpyToSymbolAsync(c_w, Kw, 81 * sizeof(float), 0, cudaMemcpyDeviceToDevice, 0);
    cudaMemcpyToSymbolAsync(c_b, Bb, 3 * sizeof(float), 0, cudaMemcpyDeviceToDevice, 0);

    dim3 grid(IMG_W / TILE_W, IMG_H / TILE_H, 32);
    patchenc_v4_kernel<<<grid, 128>>>(X, PE, (float*)d_out);
}

// round 10
// speedup vs baseline: 1.5651x; 1.5651x over previous
#include <cuda_runtime.h>
#include <cstddef>

#define IMG_H 512
#define IMG_W 512
#define IMGF  (IMG_H * IMG_W * 3)
#define TILE_W 64
#define TILE_H 32
#define NP_TOT 1024
#define OUTF_PER_B (NP_TOT * 768)     // 786432 floats per batch

__constant__ float c_w[81];   // [ky][kx][ci][co] HWIO
__constant__ float c_b[3];

// Output-linear permuted copy of pos_emb (batch-independent), 3 MB.
__device__ float d_pe_perm[OUTF_PER_B];

// ---- prep: pe_perm[np*768 + r*48 + px*3 + c] = pos_emb[nf*48 + pof] ----
__global__ __launch_bounds__(256)
void pe_permute_kernel(const float* __restrict__ pos_emb)
{
    const int j4 = blockIdx.x * 256 + threadIdx.x;   // float4 index, < 196608
    const int j0 = j4 * 4;
    float v[4];
#pragma unroll
    for (int t = 0; t < 4; t++) {
        const int j  = j0 + t;
        const int np = j / 768;                      // FIXED (was j>>10)
        const int rm = j - np * 768;
        const int r  = rm / 48;                      // row in patch 0..15
        const int k  = rm - r * 48;
        const int px = k / 3;                        // col in patch 0..15
        const int c  = k - px * 3;
        const int gh = ((np >> 5) << 4) + r;
        const int gw = ((np & 31) << 4) + px;
        const int nf  = (gh >> 2) * 128 + (gw >> 2);
        const int pof = (gh & 3) * 12 + (gw & 3) * 3 + c;
        v[t] = pos_emb[nf * 48 + pof];
    }
    *(float4*)&d_pe_perm[j0] = make_float4(v[0], v[1], v[2], v[3]);
}

__device__ __forceinline__ void load_row_g(const float* __restrict__ Xb,
                                           int row_off, bool rvalid,
                                           bool zl, bool zr, float f[20])
{
#pragma unroll
    for (int j = 0; j < 5; j++) {
        float4 v = make_float4(0.f, 0.f, 0.f, 0.f);
        const int g = row_off + 4 * j;
        if (rvalid && g >= 0 && g + 3 < IMGF)
            v = *(const float4*)(Xb + g);
        f[4*j+0] = v.x; f[4*j+1] = v.y; f[4*j+2] = v.z; f[4*j+3] = v.w;
    }
    if (zl) { f[1]  = 0.f; f[2]  = 0.f; f[3]  = 0.f; }
    if (zr) { f[16] = 0.f; f[17] = 0.f; f[18] = 0.f; }
}

__device__ __forceinline__ void apply_row(const float f[20], float acc[12], const int wrow)
{
#pragma unroll
    for (int x = 0; x < 4; x++) {
#pragma unroll
        for (int dx = 0; dx < 3; dx++) {
#pragma unroll
            for (int ci = 0; ci < 3; ci++) {
                const float v = f[3*(x + dx) + ci + 1];
                const int wb = ((wrow*3 + dx)*3 + ci)*3;
                acc[x*3 + 0] += v * c_w[wb + 0];
                acc[x*3 + 1] += v * c_w[wb + 1];
                acc[x*3 + 2] += v * c_w[wb + 2];
            }
        }
    }
}

__global__ __launch_bounds__(256, 4)
void patchenc_v5_kernel(const float* __restrict__ X,
                        float* __restrict__ out)
{
    // 64x32 tile = 2 patch bands x 4 patches = 8 patches, output-ordered.
    __shared__ float4 sout4[1536];   // 24 KB

    const int b  = blockIdx.z;
    const int h0 = blockIdx.y * TILE_H;
    const int w0 = blockIdx.x * TILE_W;
    const float* __restrict__ Xb = X + (size_t)b * IMGF;

    const int txq = threadIdx.x & 15;     // gw0 = w0 + 4*txq
    const int tyq = threadIdx.x >> 4;     // 0..15, gh0 = h0 + 2*tyq
    const int gh0 = h0 + 2 * tyq;

    const bool zl = (w0 == 0) && (txq == 0);
    const bool zr = (w0 == IMG_W - TILE_W) && (txq == 15);

    const int base_off = 3 * w0 + 12 * txq - 4;
    const int ROWF = 3 * IMG_W;

    float acc0[12], acc1[12];
#pragma unroll
    for (int x = 0; x < 4; x++)
#pragma unroll
        for (int c = 0; c < 3; c++) { acc0[x*3+c] = c_b[c]; acc1[x*3+c] = c_b[c]; }

    float f[20];
    {
        const int r = gh0 - 1;
        load_row_g(Xb, base_off + r * ROWF, r >= 0, zl, zr, f);
        apply_row(f, acc0, 0);
    }
    {
        load_row_g(Xb, base_off + gh0 * ROWF, true, zl, zr, f);
        apply_row(f, acc0, 1);
        apply_row(f, acc1, 0);
    }
    {
        load_row_g(Xb, base_off + (gh0 + 1) * ROWF, true, zl, zr, f);
        apply_row(f, acc0, 2);
        apply_row(f, acc1, 1);
    }
    {
        const int r = gh0 + 2;
        load_row_g(Xb, base_off + r * ROWF, r < IMG_H, zl, zr, f);
        apply_row(f, acc1, 2);
    }

    // ---- stage into output-ordered smem ----
    // sout4 index: band*768 + pch*192 + (gh&15)*12 + (txq&3)*3
    const int band = tyq >> 3;
    const int pch  = txq >> 2;
#pragma unroll
    for (int k = 0; k < 2; k++) {
        const float* acc = (k == 0) ? acc0 : acc1;
        const int gh = gh0 + k;
        float4* so = &sout4[band * 768 + pch * 192 + (gh & 15) * 12 + (txq & 3) * 3];
        so[0] = make_float4(acc[0], acc[1],  acc[2],  acc[3]);
        so[1] = make_float4(acc[4], acc[5],  acc[6],  acc[7]);
        so[2] = make_float4(acc[8], acc[9],  acc[10], acc[11]);
    }

    __syncthreads();

    // ---- linear copy-out fused with linear PE add ----
    // band bd covers np = ((h0>>4)+bd)*32 + (w0>>4) + 0..3 (contiguous)
    const int npb0 = (h0 >> 4) * 32 + (w0 >> 4);
    const float4* pe4 = (const float4*)d_pe_perm;
    float4* ob = (float4*)out + (size_t)b * (OUTF_PER_B / 4);

#pragma unroll
    for (int k = 0; k < 6; k++) {
        const int v  = threadIdx.x + k * 256;        // 0..1535
        const int bd = (v >= 768) ? 1 : 0;           // FIXED (was v>>10)
        const int rm = v - bd * 768;
        const size_t g4 = (size_t)(npb0 + bd * 32) * 192 + rm;
        float4 s = sout4[v];
        float4 p = pe4[g4];
        ob[g4] = make_float4(s.x + p.x, s.y + p.y, s.z + p.z, s.w + p.w);
    }
}

extern "C" void kernel_launch(void* const* d_in, const int* in_sizes, int n_in,
                              void* d_out, int out_size)
{
    const float* X  = (const float*)d_in[0];
    const float* Kw = (const float*)d_in[1];
    const float* Bb = (const float*)d_in[2];
    const float* PE = (const float*)d_in[3];

    cudaMemcpyToSymbolAsync(c_w, Kw, 81 * sizeof(float), 0, cudaMemcpyDeviceToDevice, 0);
    cudaMemcpyToSymbolAsync(c_b, Bb, 3 * sizeof(float), 0, cudaMemcpyDeviceToDevice, 0);

    // PE permute: 196608 float4 -> 768 blocks of 256
    pe_permute_kernel<<<768, 256>>>(PE);

    dim3 grid(IMG_W / TILE_W, IMG_H / TILE_H, 32);
    patchenc_v5_kernel<<<grid, 256>>>(X, (float*)d_out);
}